// round 7
// baseline (speedup 1.0000x reference)
#include <cuda_runtime.h>
#include <math.h>
#include <stdint.h>

#define BB 256
#define TT 1024
#define MM 64
#define KH 512

#define RTHREADS 256
#define NCTA_R 128
#define GRP_CTAS 32

#define APITCH 68
#define BPITCH 580
#define XPITCH 68
#define EPITCH 68

// float offsets into dynamic SMEM
#define OFF_B 0
#define OFF_A0 (64 * BPITCH)            // 37120
#define OFF_A1 (OFF_A0 + 64 * APITCH)   // 41472
#define OFF_A2 (OFF_A1 + 64 * APITCH)   // 45824
#define OFF_XR (OFF_A2 + 64 * APITCH)   // 50176
#define OFF_BIAS (OFF_XR + 64 * XPITCH) // 54528
#define OFF_SX (OFF_BIAS + 64)          // 54592
#define OFF_WC (OFF_SX + 64)            // 54656
#define SMEM_FLOATS (OFF_WC + 64)       // 54720
#define SMEM_BYTES (SMEM_FLOATS * 4)    // 218880

__device__ float g_hs[(size_t)TT * BB * KH];
__device__ unsigned g_cnt[4] = {0, 0, 0, 0};
__device__ unsigned g_gen[4] = {0, 0, 0, 0};

__device__ __forceinline__ uint32_t f2tf32(float x) {
    uint32_t r;
    asm("cvt.rna.tf32.f32 %0, %1;" : "=r"(r) : "f"(x));
    return r;
}
__device__ __forceinline__ uint32_t smaddr(const void* p) {
    return (uint32_t)__cvta_generic_to_shared(p);
}

#define CP_COMMIT() asm volatile("cp.async.commit_group;" ::: "memory")
#define CP_WAIT0() asm volatile("cp.async.wait_group 0;" ::: "memory")
#define CP_WAIT1() asm volatile("cp.async.wait_group 1;" ::: "memory")

// prefetch h chunk j (64 rows x 64 cols) from g_hs into Ab
__device__ __forceinline__ void prefetch_h(const float4* __restrict__ src,
                                           float* Ab, int j, int tid) {
#pragma unroll
    for (int i = 0; i < 4; i++) {
        int idx = tid + i * RTHREADS;       // < 1024
        int m = idx >> 4, q = idx & 15;
        uint32_t dst = smaddr(&Ab[m * APITCH + q * 4]);
        const float4* g = src + (size_t)m * (KH / 4) + j * 16 + q;
        asm volatile("cp.async.cg.shared.global [%0], [%1], 16;"
                     :: "r"(dst), "l"(g) : "memory");
    }
    CP_COMMIT();
}

// prefetch x_t tile (64 rows x 65 floats) rotated by a = (-t) mod 4 so the bulk
// uses 16B cp.async: column j lands at slot (j - a + 65) % 65.
__device__ __forceinline__ void prefetch_x(const float* __restrict__ xs,
                                           float* XR, int tid, int a) {
    const int nv = (65 - a) >> 2;          // full float4 groups
    const int nops = 65 - 3 * nv;          // nv vec + (65 - 4*nv) scalars
    const int m = tid >> 2;                // 0..63
    const int q = tid & 3;
    const float* row = xs + (size_t)m * (TT * 65);
    float* drow = XR + m * XPITCH;
    for (int o = q; o < nops; o += 4) {
        if (o < nv) {
            uint32_t dst = smaddr(drow + o * 4);
            const float* g = row + a + o * 4;   // 16B aligned: (t*65 + a) % 4 == 0
            asm volatile("cp.async.ca.shared.global [%0], [%1], 16;"
                         :: "r"(dst), "l"(g) : "memory");
        } else {
            int s = 4 * nv + (o - nv);
            int j = a + s; if (j >= 65) j -= 65;
            uint32_t dst = smaddr(drow + s);
            const float* g = row + j;
            asm volatile("cp.async.ca.shared.global [%0], [%1], 4;"
                         :: "r"(dst), "l"(g) : "memory");
        }
    }
    CP_COMMIT();
}

// One K=64 chunk: As [64][APITCH] (rows=batch), Bk weight rows offset to this
// chunk's K. Warp tile 32x16 (8 warps, grid 2x4).
__device__ __forceinline__ void compute_chunk(const float* __restrict__ As,
                                              const float* __restrict__ Bk,
                                              int m0w, int n0w, int gid, int tig,
                                              float (&d)[2][2][4]) {
#pragma unroll
    for (int ks = 0; ks < 8; ks++) {
        const int k0 = ks * 8;
        uint32_t a[2][4];
#pragma unroll
        for (int mt = 0; mt < 2; mt++) {
            const float* ap = As + (m0w + mt * 16 + gid) * APITCH + k0 + tig;
            a[mt][0] = __float_as_uint(ap[0]);
            a[mt][1] = __float_as_uint(ap[8 * APITCH]);
            a[mt][2] = __float_as_uint(ap[4]);
            a[mt][3] = __float_as_uint(ap[8 * APITCH + 4]);
        }
        uint32_t b[2][2];
#pragma unroll
        for (int nt = 0; nt < 2; nt++) {
            const float* bp = Bk + (n0w + nt * 8 + gid) * BPITCH + k0 + tig;
            b[nt][0] = __float_as_uint(bp[0]);
            b[nt][1] = __float_as_uint(bp[4]);
        }
#pragma unroll
        for (int mt = 0; mt < 2; mt++)
#pragma unroll
            for (int nt = 0; nt < 2; nt++)
                asm volatile(
                    "mma.sync.aligned.m16n8k8.row.col.f32.tf32.tf32.f32 "
                    "{%0,%1,%2,%3}, {%4,%5,%6,%7}, {%8,%9}, {%0,%1,%2,%3};"
                    : "+f"(d[mt][nt][0]), "+f"(d[mt][nt][1]),
                      "+f"(d[mt][nt][2]), "+f"(d[mt][nt][3])
                    : "r"(a[mt][0]), "r"(a[mt][1]), "r"(a[mt][2]), "r"(a[mt][3]),
                      "r"(b[nt][0]), "r"(b[nt][1]));
    }
}

__device__ __forceinline__ float fast_sigmoid(float x) {
    return 1.0f / (1.0f + __expf(-x));
}
__device__ __forceinline__ float fast_tanh(float x) {
    x = fminf(fmaxf(x, -9.0f), 9.0f);
    float e2 = __expf(2.0f * x);
    return (e2 - 1.0f) / (e2 + 1.0f);
}

// ---------------------------------------------------------------------------
// Persistent tf32 mma.sync LSTM recurrence, 8 warps, depth-2 cp.async pipeline
// over 3 A buffers. CTA (grp,hj): batch [grp*64,+64), hidden [hj*16,+16)x4 gates.
// x column 64 handled as a rank-1 update in the epilogue.
// ---------------------------------------------------------------------------
__global__ void __launch_bounds__(RTHREADS, 1)
lstm_mma(const float* __restrict__ inputs, const float* __restrict__ W_ih,
         const float* __restrict__ W_hh, const float* __restrict__ b_ih,
         const float* __restrict__ b_hh) {
    extern __shared__ __align__(16) float sm[];
    float* Bw = sm + OFF_B;
    float* Abuf[3] = {sm + OFF_A0, sm + OFF_A1, sm + OFF_A2};
    float* XR = sm + OFF_XR;
    float* sBias = sm + OFF_BIAS;
    float* sX64 = sm + OFF_SX;
    float* sWc = sm + OFF_WC;

    const int tid = threadIdx.x;
    const int wid = tid >> 5;
    const int lane = tid & 31;
    const int gid = lane >> 2, tig = lane & 3;
    const int m0w = (wid >> 2) * 32, n0w = (wid & 3) * 16;

    const int grp = blockIdx.x >> 5;
    const int hj = blockIdx.x & 31;
    const int batch_base = grp * 64;
    const int hid_base = hj * 16;

    const float* xbase = inputs + (size_t)batch_base * (TT * 65);

    // ---- one-time: weights (tf32-rounded) + bias + x64 weight column ----
    for (int idx = tid; idx < 64 * BPITCH; idx += RTHREADS) {
        int r = idx / BPITCH, k = idx - r * BPITCH;
        int u = r >> 2, g = r & 3;
        int grow = g * KH + hid_base + u;
        float w = 0.0f;
        if (k < KH) w = W_hh[(size_t)grow * KH + k];
        else if (k < KH + 64) w = W_ih[(size_t)grow * 65 + (k - KH)];
        Bw[idx] = __uint_as_float(f2tf32(w));
    }
    for (int idx = tid; idx < 64; idx += RTHREADS) {
        int u = idx >> 2, g = idx & 3;
        int grow = g * KH + hid_base + u;
        sBias[idx] = b_ih[grow] + b_hh[grow];
        sWc[idx] = W_ih[(size_t)grow * 65 + 64];
    }

    // prime x(0): a = 0
    prefetch_x(xbase, XR, tid, 0);
    __syncthreads();

    // Replay-safe: a group release needs ALL 32 CTAs' arrivals, so g_gen[grp]
    // cannot advance past this read before our own first arrival.
    unsigned gen_base = 0;
    if (tid == 0) gen_base = atomicAdd(&g_gen[grp], 0u);
    gen_base = __shfl_sync(0xFFFFFFFF, gen_base, 0);

    float c_state[4];
#pragma unroll
    for (int i = 0; i < 4; i++) c_state[i] = 0.0f;

    for (int t = 0; t < TT; ++t) {
        const int a_t = (-t) & 3;

        float d[2][2][4];
#pragma unroll
        for (int mt = 0; mt < 2; mt++)
#pragma unroll
            for (int nt = 0; nt < 2; nt++)
#pragma unroll
                for (int i = 0; i < 4; i++) d[mt][nt][i] = 0.0f;

        // XR(t) arrived (committed at end of t-1); convert rotated cols into A0
        CP_WAIT0();
        __syncthreads();
        {
            float* A0 = Abuf[0];
            for (int idx = tid; idx < 64 * 64; idx += RTHREADS) {
                int m = idx >> 6, j = idx & 63;
                int s = j - a_t; if (s < 0) s += 65;
                A0[m * APITCH + j] = __uint_as_float(f2tf32(XR[m * XPITCH + s]));
            }
            if (tid < 64) sX64[tid] = XR[tid * XPITCH + 64 - a_t];
        }
        __syncthreads();

        // x GEMM (independent of the barrier)
        compute_chunk(Abuf[0], Bw + KH, m0w, n0w, gid, tig, d);

        const float4* src = (const float4*)(g_hs + (size_t)(t - 1) * BB * KH +
                                            (size_t)batch_base * KH);
        if (t > 0) {
            if (tid == 0) {
                unsigned target = gen_base + (unsigned)t;
                while (atomicAdd(&g_gen[grp], 0u) < target) __nanosleep(32);
                __threadfence();
            }
            __syncthreads();
            prefetch_h(src, Abuf[1], 0, tid);   // h0 -> A1
            prefetch_h(src, Abuf[2], 1, tid);   // h1 -> A2

#pragma unroll 1
            for (int j = 0; j < 8; j++) {
                if (j < 7) CP_WAIT1(); else CP_WAIT0();
                __syncthreads();
                if (j < 6) {
                    int pb = j - (j >= 3 ? 3 : 0);           // j % 3
                    prefetch_h(src, Abuf[pb], j + 2, tid);   // h_{j+2} -> A[j%3]
                }
                int cb = (j + 1) - ((j + 1) >= 3 ? 3 : 0);   // (j+1) % 3
                if (cb >= 3) cb -= 3;
                compute_chunk(Abuf[cb], Bw + j * 64, m0w, n0w, gid, tig, d);
            }
        }

        // x(t+1): committed after all h groups -> chunk waits never see DRAM
        if (t + 1 < TT) prefetch_x(xbase + (size_t)(t + 1) * 65, XR, tid, (-(t + 1)) & 3);

        // ---- epilogue: fragments -> SMEM (A0) -> cell -> h store ----
        __syncthreads();
        float* Ep = Abuf[0];
#pragma unroll
        for (int mt = 0; mt < 2; mt++)
#pragma unroll
            for (int nt = 0; nt < 2; nt++) {
                int rrow = m0w + mt * 16 + gid;
                int col = n0w + nt * 8 + tig * 2;
                Ep[rrow * EPITCH + col] = d[mt][nt][0];
                Ep[rrow * EPITCH + col + 1] = d[mt][nt][1];
                Ep[(rrow + 8) * EPITCH + col] = d[mt][nt][2];
                Ep[(rrow + 8) * EPITCH + col + 1] = d[mt][nt][3];
            }
        __syncthreads();

        float* hdst = g_hs + (size_t)t * BB * KH + (size_t)batch_base * KH + hid_base;
#pragma unroll
        for (int i = 0; i < 4; i++) {
            int idx = tid + i * RTHREADS;       // < 1024
            int m = idx >> 4, u = idx & 15;
            float4 gt = *(const float4*)&Ep[m * EPITCH + 4 * u];
            float4 wc = *(const float4*)&sWc[4 * u];
            float xm = sX64[m];
            float iv = fast_sigmoid(gt.x + xm * wc.x + sBias[4 * u + 0]);
            float fv = fast_sigmoid(gt.y + xm * wc.y + sBias[4 * u + 1]);
            float gv = fast_tanh(gt.z + xm * wc.z + sBias[4 * u + 2]);
            float ov = fast_sigmoid(gt.w + xm * wc.w + sBias[4 * u + 3]);
            float cc = fv * c_state[i] + iv * gv;
            c_state[i] = cc;
            float hv = ov * fast_tanh(cc);
            hdst[(size_t)m * KH + u] = __uint_as_float(f2tf32(hv));
        }
        __syncthreads();

        if (tid == 0) {
            __threadfence();
            unsigned old = atomicInc(&g_cnt[grp], GRP_CTAS - 1);
            if (old == GRP_CTAS - 1) atomicAdd(&g_gen[grp], 1u);
        }
    }
}

// ---------------------------------------------------------------------------
// Output projection: out[b,t,:] = hs[t,b,:] @ V_w^T + V_b
// ---------------------------------------------------------------------------
#define NTHREADS 256
#define PROJ_ROWS 64
#define PROJ_CHUNK 16
#define VPAD 68

__global__ void __launch_bounds__(NTHREADS, 1)
proj_kernel(const float* __restrict__ V_w, const float* __restrict__ V_b,
            float* __restrict__ out) {
    extern __shared__ __align__(16) float smemf[];
    float* sV = smemf;                    // [512][VPAD]
    float* sHr = sV + KH * VPAD;          // [16][512]
    float* sVb = sHr + PROJ_CHUNK * KH;   // [64]

    const int tid = threadIdx.x;
    const int mg = tid & 15;
    const int rs = tid >> 4;

    for (int idx = tid; idx < MM * KH; idx += NTHREADS) {
        int m = idx >> 9;
        int k = idx & 511;
        sV[k * VPAD + m] = V_w[idx];
    }
    for (int idx = tid; idx < MM; idx += NTHREADS) sVb[idx] = V_b[idx];
    __syncthreads();

    const int row_base = blockIdx.x * PROJ_ROWS;

    for (int ch = 0; ch < PROJ_ROWS; ch += PROJ_CHUNK) {
        const float4* src = (const float4*)(g_hs + (size_t)(row_base + ch) * KH);
        for (int idx = tid; idx < PROJ_CHUNK * (KH / 4); idx += NTHREADS) {
            ((float4*)sHr)[idx] = src[idx];
        }
        __syncthreads();

        float acc0 = sVb[mg * 4 + 0];
        float acc1 = sVb[mg * 4 + 1];
        float acc2 = sVb[mg * 4 + 2];
        float acc3 = sVb[mg * 4 + 3];
#pragma unroll 4
        for (int q = 0; q < KH / 4; q++) {
            float4 hv = *(const float4*)&sHr[rs * KH + q * 4];
            float4 v0 = *(const float4*)&sV[(q * 4 + 0) * VPAD + mg * 4];
            float4 v1 = *(const float4*)&sV[(q * 4 + 1) * VPAD + mg * 4];
            float4 v2 = *(const float4*)&sV[(q * 4 + 2) * VPAD + mg * 4];
            float4 v3 = *(const float4*)&sV[(q * 4 + 3) * VPAD + mg * 4];
            acc0 += hv.x * v0.x + hv.y * v1.x + hv.z * v2.x + hv.w * v3.x;
            acc1 += hv.x * v0.y + hv.y * v1.y + hv.z * v2.y + hv.w * v3.y;
            acc2 += hv.x * v0.z + hv.y * v1.z + hv.z * v2.z + hv.w * v3.z;
            acc3 += hv.x * v0.w + hv.y * v1.w + hv.z * v2.w + hv.w * v3.w;
        }

        int row = row_base + ch + rs;   // linear = t*B + b
        int t = row >> 8;
        int b = row & 255;
        float4 o = make_float4(acc0, acc1, acc2, acc3);
        *(float4*)&out[((size_t)b * TT + t) * MM + mg * 4] = o;
        __syncthreads();
    }
}

extern "C" void kernel_launch(void* const* d_in, const int* in_sizes, int n_in,
                              void* d_out, int out_size) {
    const float* inputs = (const float*)d_in[0];
    const float* W_ih   = (const float*)d_in[1];
    const float* W_hh   = (const float*)d_in[2];
    const float* b_ih   = (const float*)d_in[3];
    const float* b_hh   = (const float*)d_in[4];
    const float* V_w    = (const float*)d_in[5];
    const float* V_b    = (const float*)d_in[6];
    float* out = (float*)d_out;

    const int smem2 = (KH * VPAD + PROJ_CHUNK * KH + 64) * (int)sizeof(float);

    cudaFuncSetAttribute(lstm_mma, cudaFuncAttributeMaxDynamicSharedMemorySize,
                         SMEM_BYTES);
    cudaFuncSetAttribute(proj_kernel, cudaFuncAttributeMaxDynamicSharedMemorySize,
                         smem2);

    lstm_mma<<<NCTA_R, RTHREADS, SMEM_BYTES>>>(inputs, W_ih, W_hh, b_ih, b_hh);
    proj_kernel<<<(BB * TT) / PROJ_ROWS, NTHREADS, smem2>>>(V_w, V_b, out);
}

// round 8
// speedup vs baseline: 1.1438x; 1.1438x over previous
#include <cuda_runtime.h>
#include <math.h>
#include <stdint.h>

#define BB 256
#define TT 1024
#define MM 64
#define KH 512

#define RTHREADS 128
#define NCTA_R 128
#define GRP_CTAS 32

#define APITCH 76
#define BPITCH 644
#define XPITCH 68
#define EPITCH 68

// float-offsets into dynamic SMEM
#define OFF_B 0
#define OFF_A0 (64 * BPITCH)                  // 41216
#define OFF_A1 (OFF_A0 + 64 * APITCH)         // 46080
#define OFF_XR (OFF_A1 + 64 * APITCH)         // 50944
#define OFF_BIAS (OFF_XR + 64 * XPITCH)       // 55296
#define SMEM_FLOATS (OFF_BIAS + 64)
#define SMEM_BYTES (SMEM_FLOATS * 4)          // 221440

__device__ float g_hs[(size_t)TT * BB * KH];
// per-CTA progress flags, one 128B line each: g_flag[grp][cta*32]
__device__ unsigned g_flag[4][GRP_CTAS * 32];

__device__ __forceinline__ uint32_t f2tf32(float x) {
    uint32_t r;
    asm("cvt.rna.tf32.f32 %0, %1;" : "=r"(r) : "f"(x));
    return r;
}
__device__ __forceinline__ uint32_t smaddr(const void* p) {
    return (uint32_t)__cvta_generic_to_shared(p);
}
__device__ __forceinline__ unsigned ld_acq(const unsigned* p) {
    unsigned v;
    asm volatile("ld.acquire.gpu.global.u32 %0, [%1];" : "=r"(v) : "l"(p) : "memory");
    return v;
}
__device__ __forceinline__ void st_rel(unsigned* p, unsigned v) {
    asm volatile("st.release.gpu.global.u32 [%0], %1;" :: "l"(p), "r"(v) : "memory");
}

#define CP_COMMIT() asm volatile("cp.async.commit_group;" ::: "memory")
#define CP_WAIT0() asm volatile("cp.async.wait_group 0;" ::: "memory")

// prefetch h chunk j (64 rows x 64 cols) from g_hs into Ab
__device__ __forceinline__ void prefetch_h(const float4* __restrict__ src,
                                           float* Ab, int j, int tid) {
#pragma unroll
    for (int i = 0; i < 8; i++) {
        int idx = tid + i * RTHREADS;
        int m = idx >> 4, q = idx & 15;
        uint32_t dst = smaddr(&Ab[m * APITCH + q * 4]);
        const float4* g = src + (size_t)m * (KH / 4) + j * 16 + q;
        asm volatile("cp.async.cg.shared.global [%0], [%1], 16;"
                     :: "r"(dst), "l"(g) : "memory");
    }
    CP_COMMIT();
}

// prefetch raw x_t tile (64 rows x 65 floats) into XR (4B granules: row base
// offsets are t*260 bytes -> only 4B aligned)
__device__ __forceinline__ void prefetch_x(const float* __restrict__ xs,
                                           float* XR, int tid) {
    for (int idx = tid; idx < 64 * 65; idx += RTHREADS) {
        int m = idx / 65, j = idx - m * 65;
        uint32_t dst = smaddr(&XR[m * XPITCH + j]);
        const float* g = xs + (size_t)m * (TT * 65) + j;
        asm volatile("cp.async.ca.shared.global [%0], [%1], 4;"
                     :: "r"(dst), "l"(g) : "memory");
    }
    CP_COMMIT();
}

// One K-chunk of the gate GEMM. As: [64][APITCH] rows=batch; Bk: weight rows
// [64][BPITCH] offset to this chunk's K columns. Warp tile 32x32 (4 warps).
template <int NKS>
__device__ __forceinline__ void compute_chunk(const float* __restrict__ As,
                                              const float* __restrict__ Bk,
                                              int m0w, int n0w, int gid, int tig,
                                              float (&d)[2][4][4]) {
#pragma unroll
    for (int ks = 0; ks < NKS; ks++) {
        const int k0 = ks * 8;
        uint32_t a[2][4];
#pragma unroll
        for (int mt = 0; mt < 2; mt++) {
            const float* ap = As + (m0w + mt * 16 + gid) * APITCH + k0 + tig;
            a[mt][0] = __float_as_uint(ap[0]);
            a[mt][1] = __float_as_uint(ap[8 * APITCH]);
            a[mt][2] = __float_as_uint(ap[4]);
            a[mt][3] = __float_as_uint(ap[8 * APITCH + 4]);
        }
        uint32_t b[4][2];
#pragma unroll
        for (int nt = 0; nt < 4; nt++) {
            const float* bp = Bk + (n0w + nt * 8 + gid) * BPITCH + k0 + tig;
            b[nt][0] = __float_as_uint(bp[0]);
            b[nt][1] = __float_as_uint(bp[4]);
        }
#pragma unroll
        for (int mt = 0; mt < 2; mt++)
#pragma unroll
            for (int nt = 0; nt < 4; nt++)
                asm volatile(
                    "mma.sync.aligned.m16n8k8.row.col.f32.tf32.tf32.f32 "
                    "{%0,%1,%2,%3}, {%4,%5,%6,%7}, {%8,%9}, {%0,%1,%2,%3};"
                    : "+f"(d[mt][nt][0]), "+f"(d[mt][nt][1]),
                      "+f"(d[mt][nt][2]), "+f"(d[mt][nt][3])
                    : "r"(a[mt][0]), "r"(a[mt][1]), "r"(a[mt][2]), "r"(a[mt][3]),
                      "r"(b[nt][0]), "r"(b[nt][1]));
    }
}

__device__ __forceinline__ float fast_sigmoid(float x) {
    return 1.0f / (1.0f + __expf(-x));
}
__device__ __forceinline__ float fast_tanh(float x) {
    x = fminf(fmaxf(x, -9.0f), 9.0f);
    float e2 = __expf(2.0f * x);
    return (e2 - 1.0f) / (e2 + 1.0f);
}

// ---------------------------------------------------------------------------
// Persistent tf32 mma.sync LSTM recurrence (R6-winning structure) with a
// decentralized release/acquire flag barrier per 32-CTA batch group.
// CTA (grp,hj): batch rows [grp*64,+64), hidden units [hj*16,+16) x 4 gates.
// ---------------------------------------------------------------------------
__global__ void __launch_bounds__(RTHREADS, 1)
lstm_mma(const float* __restrict__ inputs, const float* __restrict__ W_ih,
         const float* __restrict__ W_hh, const float* __restrict__ b_ih,
         const float* __restrict__ b_hh) {
    extern __shared__ __align__(16) float sm[];
    float* Bw = sm + OFF_B;
    float* A0 = sm + OFF_A0;
    float* A1 = sm + OFF_A1;
    float* XR = sm + OFF_XR;
    float* sBias = sm + OFF_BIAS;

    const int tid = threadIdx.x;
    const int wid = tid >> 5;
    const int lane = tid & 31;
    const int gid = lane >> 2, tig = lane & 3;
    const int m0w = (wid >> 1) * 32, n0w = (wid & 1) * 32;

    const int grp = blockIdx.x >> 5;
    const int hj = blockIdx.x & 31;
    const int batch_base = grp * 64;
    const int hid_base = hj * 16;

    const float* xbase = inputs + (size_t)batch_base * (TT * 65);

    // ---- one-time: weights (tf32-rounded) + bias ----
    for (int idx = tid; idx < 64 * BPITCH; idx += RTHREADS) {
        int r = idx / BPITCH, k = idx - r * BPITCH;
        int u = r >> 2, g = r & 3;
        int grow = g * KH + hid_base + u;
        float w = 0.0f;
        if (k < KH) w = W_hh[(size_t)grow * KH + k];
        else if (k < KH + 65) w = W_ih[(size_t)grow * 65 + (k - KH)];
        Bw[idx] = __uint_as_float(f2tf32(w));
    }
    for (int idx = tid; idx < 64; idx += RTHREADS) {
        int u = idx >> 2, g = idx & 3;
        int grow = g * KH + hid_base + u;
        sBias[idx] = b_ih[grow] + b_hh[grow];
    }

    // prime x(0)
    prefetch_x(xbase, XR, tid);
    __syncthreads();

    // Flag base for this replay: all flags in the group are equal at launch
    // (every CTA completed TT steps last replay). Only warp 0 needs it.
    unsigned base = 0;
    if (wid == 0) {
        if (lane == 0) base = ld_acq(&g_flag[grp][hj * 32]);
        base = __shfl_sync(0xFFFFFFFFu, base, 0);
    }

    float c_state[8];
#pragma unroll
    for (int i = 0; i < 8; i++) c_state[i] = 0.0f;

    for (int t = 0; t < TT; ++t) {
        float d[2][4][4];
#pragma unroll
        for (int mt = 0; mt < 2; mt++)
#pragma unroll
            for (int nt = 0; nt < 4; nt++)
#pragma unroll
                for (int i = 0; i < 4; i++) d[mt][nt][i] = 0.0f;

        // XR(t) arrived (committed at end of t-1); convert into A0 (pad to 72)
        CP_WAIT0();
        __syncthreads();
        for (int idx = tid; idx < 64 * 72; idx += RTHREADS) {
            int m = idx / 72, j = idx - m * 72;
            float v = (j < 65) ? XR[m * XPITCH + j] : 0.0f;
            A0[m * APITCH + j] = __uint_as_float(f2tf32(v));
        }
        __syncthreads();

        const float4* src = (const float4*)(g_hs + (size_t)(t - 1) * BB * KH +
                                            (size_t)batch_base * KH);
        if (t > 0) {
            // wait for h(t-1): 32 lanes of warp 0 poll 32 per-CTA flags
            if (wid == 0) {
                const unsigned tgt = base + (unsigned)t;
                const unsigned* fp = &g_flag[grp][lane * 32];
                unsigned v;
                do {
                    v = ld_acq(fp);
                } while (!__all_sync(0xFFFFFFFFu, (int)(v - tgt) >= 0));
            }
            __syncthreads();
            prefetch_h(src, A1, 0, tid);   // chunk0 copy overlaps x GEMM
        }

        compute_chunk<9>(A0, Bw + KH, m0w, n0w, gid, tig, d);

        if (t > 0) {
#pragma unroll 1
            for (int j = 0; j < 8; j++) {
                CP_WAIT0();
                __syncthreads();
                if (j < 7)
                    prefetch_h(src, (j & 1) ? A1 : A0, j + 1, tid);
                compute_chunk<8>((j & 1) ? A0 : A1, Bw + j * 64, m0w, n0w, gid,
                                 tig, d);
            }
        }

        // x(t+1): committed after all h groups so chunk waits never see DRAM
        if (t + 1 < TT) prefetch_x(xbase + (size_t)(t + 1) * 65, XR, tid);

        // ---- epilogue: fragments -> SMEM (A1) -> cell -> h store ----
        float* Ep = A1;
#pragma unroll
        for (int mt = 0; mt < 2; mt++)
#pragma unroll
            for (int nt = 0; nt < 4; nt++) {
                int rrow = m0w + mt * 16 + gid;
                int col = n0w + nt * 8 + tig * 2;
                Ep[rrow * EPITCH + col] = d[mt][nt][0];
                Ep[rrow * EPITCH + col + 1] = d[mt][nt][1];
                Ep[(rrow + 8) * EPITCH + col] = d[mt][nt][2];
                Ep[(rrow + 8) * EPITCH + col + 1] = d[mt][nt][3];
            }
        __syncthreads();

        float* hdst = g_hs + (size_t)t * BB * KH + (size_t)batch_base * KH + hid_base;
#pragma unroll
        for (int i = 0; i < 8; i++) {
            int idx = tid + i * RTHREADS;
            int m = idx >> 4, u = idx & 15;
            float4 gt = *(const float4*)&Ep[m * EPITCH + 4 * u];
            float iv = fast_sigmoid(gt.x + sBias[4 * u + 0]);
            float fv = fast_sigmoid(gt.y + sBias[4 * u + 1]);
            float gv = fast_tanh(gt.z + sBias[4 * u + 2]);
            float ov = fast_sigmoid(gt.w + sBias[4 * u + 3]);
            float cc = fv * c_state[i] + iv * gv;
            c_state[i] = cc;
            float hv = ov * fast_tanh(cc);
            hdst[(size_t)m * KH + u] = __uint_as_float(f2tf32(hv));
        }
        __syncthreads();   // all h stores of this CTA done before the release

        if (tid == 0) {
            // release-store: bar.sync + st.release orders every thread's h
            // stores before the flag update (standard morally-strong chain)
            st_rel(&g_flag[grp][hj * 32], base + (unsigned)t + 1u);
        }
    }
}

// ---------------------------------------------------------------------------
// Output projection: out[b,t,:] = hs[t,b,:] @ V_w^T + V_b
// ---------------------------------------------------------------------------
#define NTHREADS 256
#define PROJ_ROWS 64
#define PROJ_CHUNK 16
#define VPAD 68

__global__ void __launch_bounds__(NTHREADS, 1)
proj_kernel(const float* __restrict__ V_w, const float* __restrict__ V_b,
            float* __restrict__ out) {
    extern __shared__ __align__(16) float smemf[];
    float* sV = smemf;                    // [512][VPAD]
    float* sHr = sV + KH * VPAD;          // [16][512]
    float* sVb = sHr + PROJ_CHUNK * KH;   // [64]

    const int tid = threadIdx.x;
    const int mg = tid & 15;
    const int rs = tid >> 4;

    for (int idx = tid; idx < MM * KH; idx += NTHREADS) {
        int m = idx >> 9;
        int k = idx & 511;
        sV[k * VPAD + m] = V_w[idx];
    }
    for (int idx = tid; idx < MM; idx += NTHREADS) sVb[idx] = V_b[idx];
    __syncthreads();

    const int row_base = blockIdx.x * PROJ_ROWS;

    for (int ch = 0; ch < PROJ_ROWS; ch += PROJ_CHUNK) {
        const float4* src = (const float4*)(g_hs + (size_t)(row_base + ch) * KH);
        for (int idx = tid; idx < PROJ_CHUNK * (KH / 4); idx += NTHREADS) {
            ((float4*)sHr)[idx] = src[idx];
        }
        __syncthreads();

        float acc0 = sVb[mg * 4 + 0];
        float acc1 = sVb[mg * 4 + 1];
        float acc2 = sVb[mg * 4 + 2];
        float acc3 = sVb[mg * 4 + 3];
#pragma unroll 4
        for (int q = 0; q < KH / 4; q++) {
            float4 hv = *(const float4*)&sHr[rs * KH + q * 4];
            float4 v0 = *(const float4*)&sV[(q * 4 + 0) * VPAD + mg * 4];
            float4 v1 = *(const float4*)&sV[(q * 4 + 1) * VPAD + mg * 4];
            float4 v2 = *(const float4*)&sV[(q * 4 + 2) * VPAD + mg * 4];
            float4 v3 = *(const float4*)&sV[(q * 4 + 3) * VPAD + mg * 4];
            acc0 += hv.x * v0.x + hv.y * v1.x + hv.z * v2.x + hv.w * v3.x;
            acc1 += hv.x * v0.y + hv.y * v1.y + hv.z * v2.y + hv.w * v3.y;
            acc2 += hv.x * v0.z + hv.y * v1.z + hv.z * v2.z + hv.w * v3.z;
            acc3 += hv.x * v0.w + hv.y * v1.w + hv.z * v2.w + hv.w * v3.w;
        }

        int row = row_base + ch + rs;   // linear = t*B + b
        int t = row >> 8;
        int b = row & 255;
        float4 o = make_float4(acc0, acc1, acc2, acc3);
        *(float4*)&out[((size_t)b * TT + t) * MM + mg * 4] = o;
        __syncthreads();
    }
}

extern "C" void kernel_launch(void* const* d_in, const int* in_sizes, int n_in,
                              void* d_out, int out_size) {
    const float* inputs = (const float*)d_in[0];
    const float* W_ih   = (const float*)d_in[1];
    const float* W_hh   = (const float*)d_in[2];
    const float* b_ih   = (const float*)d_in[3];
    const float* b_hh   = (const float*)d_in[4];
    const float* V_w    = (const float*)d_in[5];
    const float* V_b    = (const float*)d_in[6];
    float* out = (float*)d_out;

    const int smem2 = (KH * VPAD + PROJ_CHUNK * KH + 64) * (int)sizeof(float);

    cudaFuncSetAttribute(lstm_mma, cudaFuncAttributeMaxDynamicSharedMemorySize,
                         SMEM_BYTES);
    cudaFuncSetAttribute(proj_kernel, cudaFuncAttributeMaxDynamicSharedMemorySize,
                         smem2);

    lstm_mma<<<NCTA_R, RTHREADS, SMEM_BYTES>>>(inputs, W_ih, W_hh, b_ih, b_hh);
    proj_kernel<<<(BB * TT) / PROJ_ROWS, NTHREADS, smem2>>>(V_w, V_b, out);
}

// round 12
// speedup vs baseline: 1.3391x; 1.1707x over previous
#include <cuda_runtime.h>
#include <math.h>
#include <stdint.h>

#define BB 256
#define TT 1024
#define MM 64
#define KH 512

#define RTHREADS 256
#define NCTA_R 128
#define GRP_CTAS 32

#define APITCH 68       // K=64 h-chunk pitch (68 % 32 == 4 -> conflict-free)
#define BPITCH 516      // W_hh row pitch    (516 % 32 == 4)
#define XPITCH 76       // x tile / W_ih pitch (76 % 32 == 12 -> conflict-free)
#define EPITCH 68

// float offsets into recurrence dynamic SMEM
#define OFF_WHH 0
#define OFF_WIH (64 * BPITCH)               // 33024
#define OFF_A0 (OFF_WIH + 64 * XPITCH)      // 37888
#define OFF_A1 (OFF_A0 + 64 * APITCH)       // 42240
#define OFF_AX (OFF_A1 + 64 * APITCH)       // 46592
#define OFF_BIAS (OFF_AX + 64 * XPITCH)     // 51456
#define SMEM_FLOATS (OFF_BIAS + 64)
#define SMEM_BYTES (SMEM_FLOATS * 4)        // 206080

__device__ float g_hs[(size_t)TT * BB * KH];
// tf32-converted, transposed, padded x: [grp][t][m=64][72]  (75.5 MB)
__device__ float g_xt[(size_t)4 * TT * 64 * 72];
// per-CTA progress flags, one 128B line each
__device__ unsigned g_flag[4][GRP_CTAS * 32];

__device__ __forceinline__ uint32_t f2tf32(float x) {
    uint32_t r;
    asm("cvt.rna.tf32.f32 %0, %1;" : "=r"(r) : "f"(x));
    return r;
}
__device__ __forceinline__ uint32_t smaddr(const void* p) {
    return (uint32_t)__cvta_generic_to_shared(p);
}
__device__ __forceinline__ unsigned ld_acq(const unsigned* p) {
    unsigned v;
    asm volatile("ld.acquire.gpu.global.u32 %0, [%1];" : "=r"(v) : "l"(p) : "memory");
    return v;
}
__device__ __forceinline__ void st_rel(unsigned* p, unsigned v) {
    asm volatile("st.release.gpu.global.u32 [%0], %1;" :: "l"(p), "r"(v) : "memory");
}

#define CP_COMMIT() asm volatile("cp.async.commit_group;" ::: "memory")
#define CP_WAIT0() asm volatile("cp.async.wait_group 0;" ::: "memory")
#define CP_WAIT1() asm volatile("cp.async.wait_group 1;" ::: "memory")

// prefetch h chunk j (64 rows x 64 cols) from g_hs into Ab
__device__ __forceinline__ void prefetch_h(const float4* __restrict__ src,
                                           float* Ab, int j, int tid) {
#pragma unroll
    for (int i = 0; i < 4; i++) {
        int idx = tid + i * RTHREADS;       // < 1024
        int m = idx >> 4, q = idx & 15;
        uint32_t dst = smaddr(&Ab[m * APITCH + q * 4]);
        const float4* g = src + (size_t)m * (KH / 4) + j * 16 + q;
        asm volatile("cp.async.cg.shared.global [%0], [%1], 16;"
                     :: "r"(dst), "l"(g) : "memory");
    }
    CP_COMMIT();
}

// prefetch precomputed x tile (64 x 72 tf32, contiguous) into AX
__device__ __forceinline__ void prefetch_ax(const float4* __restrict__ src,
                                            float* AX, int tid) {
#pragma unroll
    for (int i = 0; i < 5; i++) {
        int idx = tid + i * RTHREADS;
        if (idx < 1152) {                  // 64 rows x 18 float4
            int m = idx / 18, q = idx - m * 18;
            uint32_t dst = smaddr(&AX[m * XPITCH + q * 4]);
            asm volatile("cp.async.cg.shared.global [%0], [%1], 16;"
                         :: "r"(dst), "l"(src + idx) : "memory");
        }
    }
    CP_COMMIT();
}

// K-step range [KS0,KS1) of a gate GEMM chunk. As: [64][AP] rows=M;
// Bk: [64][BP] rows=N. Warp tile 32x32; two k-half warp sets (split-K).
template <int KS0, int KS1, int AP, int BP>
__device__ __forceinline__ void compute_chunk(const float* __restrict__ As,
                                              const float* __restrict__ Bk,
                                              int m0w, int n0w, int gid, int tig,
                                              float (&d)[2][4][4]) {
#pragma unroll
    for (int ks = KS0; ks < KS1; ks++) {
        const int k0 = ks * 8;
        uint32_t a[2][4];
#pragma unroll
        for (int mt = 0; mt < 2; mt++) {
            const float* ap = As + (m0w + mt * 16 + gid) * AP + k0 + tig;
            a[mt][0] = __float_as_uint(ap[0]);
            a[mt][1] = __float_as_uint(ap[8 * AP]);
            a[mt][2] = __float_as_uint(ap[4]);
            a[mt][3] = __float_as_uint(ap[8 * AP + 4]);
        }
        uint32_t b[4][2];
#pragma unroll
        for (int nt = 0; nt < 4; nt++) {
            const float* bp = Bk + (n0w + nt * 8 + gid) * BP + k0 + tig;
            b[nt][0] = __float_as_uint(bp[0]);
            b[nt][1] = __float_as_uint(bp[4]);
        }
#pragma unroll
        for (int mt = 0; mt < 2; mt++)
#pragma unroll
            for (int nt = 0; nt < 4; nt++)
                asm volatile(
                    "mma.sync.aligned.m16n8k8.row.col.f32.tf32.tf32.f32 "
                    "{%0,%1,%2,%3}, {%4,%5,%6,%7}, {%8,%9}, {%0,%1,%2,%3};"
                    : "+f"(d[mt][nt][0]), "+f"(d[mt][nt][1]),
                      "+f"(d[mt][nt][2]), "+f"(d[mt][nt][3])
                    : "r"(a[mt][0]), "r"(a[mt][1]), "r"(a[mt][2]), "r"(a[mt][3]),
                      "r"(b[nt][0]), "r"(b[nt][1]));
    }
}

__device__ __forceinline__ float fast_sigmoid(float x) {
    return 1.0f / (1.0f + __expf(-x));
}
__device__ __forceinline__ float fast_tanh(float x) {
    x = fminf(fmaxf(x, -9.0f), 9.0f);
    float e2 = __expf(2.0f * x);
    return (e2 - 1.0f) / (e2 + 1.0f);
}

// ---------------------------------------------------------------------------
// x transpose/convert precompute: g_xt[grp][t][m][j] = tf32(x[grp*64+m, t, j])
// for j<65, 0 for 65<=j<72. grid (TT, 4), 128 threads.
// ---------------------------------------------------------------------------
__global__ void __launch_bounds__(128)
xt_kernel(const float* __restrict__ inputs) {
    const int t = blockIdx.x;
    const int grp = blockIdx.y;
    float* dst = g_xt + ((size_t)grp * TT + t) * (64 * 72);
    const float* src = inputs + (size_t)grp * 64 * (TT * 65) + (size_t)t * 65;
    for (int idx = threadIdx.x; idx < 64 * 72; idx += 128) {
        int m = idx / 72, j = idx - m * 72;
        float v = (j < 65) ? src[(size_t)m * (TT * 65) + j] : 0.0f;
        dst[idx] = __uint_as_float(f2tf32(v));
    }
}

// ---------------------------------------------------------------------------
// Persistent tf32 mma.sync LSTM recurrence. 8 warps: warp w has k-half
// kh=w>>2 (split-K) and 2x2 grid position wq=w&3. Per step: x chunk (from
// precomputed AX) + 8 K=64 h chunks (depth-1 double buffer); epilogue sums
// the two k-half partials from Ep0/Ep1 (=A0/A1) + bias; flag barrier.
// ---------------------------------------------------------------------------
__global__ void __launch_bounds__(RTHREADS, 1)
lstm_mma(const float* __restrict__ W_ih, const float* __restrict__ W_hh,
         const float* __restrict__ b_ih, const float* __restrict__ b_hh) {
    extern __shared__ __align__(16) float sm[];
    float* Whh = sm + OFF_WHH;
    float* Wih = sm + OFF_WIH;
    float* A0 = sm + OFF_A0;
    float* A1 = sm + OFF_A1;
    float* AX = sm + OFF_AX;
    float* sBias = sm + OFF_BIAS;

    const int tid = threadIdx.x;
    const int wid = tid >> 5;
    const int lane = tid & 31;
    const int gid = lane >> 2, tig = lane & 3;
    const int kh = wid >> 2;                 // k-half 0/1
    const int wq = wid & 3;
    const int m0w = (wq >> 1) * 32, n0w = (wq & 1) * 32;

    const int grp = blockIdx.x >> 5;
    const int hj = blockIdx.x & 31;
    const int batch_base = grp * 64;
    const int hid_base = hj * 16;

    const float4* xt_base =
        (const float4*)(g_xt + (size_t)grp * TT * (64 * 72));

    // ---- one-time: weights (tf32-rounded) + bias ----
    for (int idx = tid; idx < 64 * BPITCH; idx += RTHREADS) {
        int r = idx / BPITCH, k = idx - r * BPITCH;
        int u = r >> 2, g = r & 3;
        int grow = g * KH + hid_base + u;
        Whh[idx] = (k < KH)
            ? __uint_as_float(f2tf32(W_hh[(size_t)grow * KH + k])) : 0.0f;
    }
    for (int idx = tid; idx < 64 * XPITCH; idx += RTHREADS) {
        int r = idx / XPITCH, k = idx - r * XPITCH;
        int u = r >> 2, g = r & 3;
        int grow = g * KH + hid_base + u;
        Wih[idx] = (k < 65)
            ? __uint_as_float(f2tf32(W_ih[(size_t)grow * 65 + k])) : 0.0f;
    }
    for (int idx = tid; idx < 64; idx += RTHREADS) {
        int u = idx >> 2, g = idx & 3;
        int grow = g * KH + hid_base + u;
        sBias[idx] = b_ih[grow] + b_hh[grow];
    }

    // prime AX(0)
    prefetch_ax(xt_base, AX, tid);
    __syncthreads();

    // Replay-safe flag base (group release needs all 32 CTAs' arrivals)
    unsigned base = 0;
    if (wid == 0) {
        if (lane == 0) base = ld_acq(&g_flag[grp][hj * 32]);
        base = __shfl_sync(0xFFFFFFFFu, base, 0);
    }

    const int mcell = tid >> 2;          // epilogue: batch row
    const int qu = tid & 3;              // epilogue: unit quad
    float c_state[4];
#pragma unroll
    for (int i = 0; i < 4; i++) c_state[i] = 0.0f;

    for (int t = 0; t < TT; ++t) {
        float d[2][4][4];
#pragma unroll
        for (int mt = 0; mt < 2; mt++)
#pragma unroll
            for (int nt = 0; nt < 4; nt++)
#pragma unroll
                for (int i = 0; i < 4; i++) d[mt][nt][i] = 0.0f;

        if (t > 0) {
            // wait for h(t-1): 32 lanes of warp 0 poll the 32 per-CTA flags
            if (wid == 0) {
                const unsigned tgt = base + (unsigned)t;
                const unsigned* fp = &g_flag[grp][lane * 32];
                unsigned v;
                do {
                    v = ld_acq(fp);
                } while (!__all_sync(0xFFFFFFFFu, (int)(v - tgt) >= 0));
            }
            __syncthreads();

            const float4* src = (const float4*)(g_hs + (size_t)(t - 1) * BB * KH +
                                                (size_t)batch_base * KH);
            prefetch_h(src, A0, 0, tid);       // chunk0 (group after AX)
            CP_WAIT1();                        // AX(t) done; chunk0 in flight
            __syncthreads();

            // x GEMM (overlaps chunk0's cp.async flight)
            if (kh == 0)
                compute_chunk<0, 5, XPITCH, XPITCH>(AX, Wih, m0w, n0w, gid, tig, d);
            else
                compute_chunk<5, 9, XPITCH, XPITCH>(AX, Wih, m0w, n0w, gid, tig, d);

#pragma unroll 1
            for (int j = 0; j < 8; j++) {
                CP_WAIT0();
                __syncthreads();
                if (j < 7)
                    prefetch_h(src, (j & 1) ? A0 : A1, j + 1, tid);
                const float* Ab = (j & 1) ? A1 : A0;
                if (kh == 0)
                    compute_chunk<0, 4, APITCH, BPITCH>(Ab, Whh + j * 64, m0w,
                                                        n0w, gid, tig, d);
                else
                    compute_chunk<4, 8, APITCH, BPITCH>(Ab, Whh + j * 64, m0w,
                                                        n0w, gid, tig, d);
            }
        } else {
            CP_WAIT0();                        // AX(0)
            __syncthreads();
            if (kh == 0)
                compute_chunk<0, 5, XPITCH, XPITCH>(AX, Wih, m0w, n0w, gid, tig, d);
            else
                compute_chunk<5, 9, XPITCH, XPITCH>(AX, Wih, m0w, n0w, gid, tig, d);
        }
        __syncthreads();   // all warps done reading A0/A1 before Ep writes

        // ---- epilogue: k-half partials -> Ep0/Ep1 (=A0/A1) -> cell ----
        float* Ep = kh ? A1 : A0;
#pragma unroll
        for (int mt = 0; mt < 2; mt++)
#pragma unroll
            for (int nt = 0; nt < 4; nt++) {
                int rrow = m0w + mt * 16 + gid;
                int col = n0w + nt * 8 + tig * 2;
                Ep[rrow * EPITCH + col] = d[mt][nt][0];
                Ep[rrow * EPITCH + col + 1] = d[mt][nt][1];
                Ep[(rrow + 8) * EPITCH + col] = d[mt][nt][2];
                Ep[(rrow + 8) * EPITCH + col + 1] = d[mt][nt][3];
            }
        __syncthreads();

        {
            float* hdst = g_hs + (size_t)t * BB * KH +
                          (size_t)(batch_base + mcell) * KH + hid_base + qu * 4;
            float hv4[4];
#pragma unroll
            for (int i = 0; i < 4; i++) {
                int u = qu * 4 + i;
                float4 gA = *(const float4*)&A0[mcell * EPITCH + 4 * u];
                float4 gB = *(const float4*)&A1[mcell * EPITCH + 4 * u];
                float4 bb = *(const float4*)&sBias[4 * u];
                float iv = fast_sigmoid(gA.x + gB.x + bb.x);
                float fv = fast_sigmoid(gA.y + gB.y + bb.y);
                float gv = fast_tanh(gA.z + gB.z + bb.z);
                float ov = fast_sigmoid(gA.w + gB.w + bb.w);
                float cc = fv * c_state[i] + iv * gv;
                c_state[i] = cc;
                hv4[i] = __uint_as_float(f2tf32(ov * fast_tanh(cc)));
            }
            *(float4*)hdst = make_float4(hv4[0], hv4[1], hv4[2], hv4[3]);
        }
        __syncthreads();   // Ep reads + h stores done before release/refill

        if (tid == 0) {
            st_rel(&g_flag[grp][hj * 32], base + (unsigned)t + 1u);
        }
        // AX(t+1): lands during barrier window; first group next step
        if (t + 1 < TT)
            prefetch_ax(xt_base + (size_t)(t + 1) * (64 * 18), AX, tid);
    }
}

// ---------------------------------------------------------------------------
// Output projection: out[b,t,:] = hs[t,b,:] @ V_w^T + V_b
// ---------------------------------------------------------------------------
#define NTHREADS 256
#define PROJ_ROWS 64
#define PROJ_CHUNK 16
#define VPAD 68

__global__ void __launch_bounds__(NTHREADS, 1)
proj_kernel(const float* __restrict__ V_w, const float* __restrict__ V_b,
            float* __restrict__ out) {
    extern __shared__ __align__(16) float smemf[];
    float* sV = smemf;                    // [512][VPAD]
    float* sHr = sV + KH * VPAD;          // [16][512]
    float* sVb = sHr + PROJ_CHUNK * KH;   // [64]

    const int tid = threadIdx.x;
    const int mg = tid & 15;
    const int rs = tid >> 4;

    for (int idx = tid; idx < MM * KH; idx += NTHREADS) {
        int m = idx >> 9;
        int k = idx & 511;
        sV[k * VPAD + m] = V_w[idx];
    }
    for (int idx = tid; idx < MM; idx += NTHREADS) sVb[idx] = V_b[idx];
    __syncthreads();

    const int row_base = blockIdx.x * PROJ_ROWS;

    for (int ch = 0; ch < PROJ_ROWS; ch += PROJ_CHUNK) {
        const float4* src = (const float4*)(g_hs + (size_t)(row_base + ch) * KH);
        for (int idx = tid; idx < PROJ_CHUNK * (KH / 4); idx += NTHREADS) {
            ((float4*)sHr)[idx] = src[idx];
        }
        __syncthreads();

        float acc0 = sVb[mg * 4 + 0];
        float acc1 = sVb[mg * 4 + 1];
        float acc2 = sVb[mg * 4 + 2];
        float acc3 = sVb[mg * 4 + 3];
#pragma unroll 4
        for (int q = 0; q < KH / 4; q++) {
            float4 hv = *(const float4*)&sHr[rs * KH + q * 4];
            float4 v0 = *(const float4*)&sV[(q * 4 + 0) * VPAD + mg * 4];
            float4 v1 = *(const float4*)&sV[(q * 4 + 1) * VPAD + mg * 4];
            float4 v2 = *(const float4*)&sV[(q * 4 + 2) * VPAD + mg * 4];
            float4 v3 = *(const float4*)&sV[(q * 4 + 3) * VPAD + mg * 4];
            acc0 += hv.x * v0.x + hv.y * v1.x + hv.z * v2.x + hv.w * v3.x;
            acc1 += hv.x * v0.y + hv.y * v1.y + hv.z * v2.y + hv.w * v3.y;
            acc2 += hv.x * v0.z + hv.y * v1.z + hv.z * v2.z + hv.w * v3.z;
            acc3 += hv.x * v0.w + hv.y * v1.w + hv.z * v2.w + hv.w * v3.w;
        }

        int row = row_base + ch + rs;   // linear = t*B + b
        int t = row >> 8;
        int b = row & 255;
        float4 o = make_float4(acc0, acc1, acc2, acc3);
        *(float4*)&out[((size_t)b * TT + t) * MM + mg * 4] = o;
        __syncthreads();
    }
}

extern "C" void kernel_launch(void* const* d_in, const int* in_sizes, int n_in,
                              void* d_out, int out_size) {
    const float* inputs = (const float*)d_in[0];
    const float* W_ih   = (const float*)d_in[1];
    const float* W_hh   = (const float*)d_in[2];
    const float* b_ih   = (const float*)d_in[3];
    const float* b_hh   = (const float*)d_in[4];
    const float* V_w    = (const float*)d_in[5];
    const float* V_b    = (const float*)d_in[6];
    float* out = (float*)d_out;

    const int smem2 = (KH * VPAD + PROJ_CHUNK * KH + 64) * (int)sizeof(float);

    cudaFuncSetAttribute(lstm_mma, cudaFuncAttributeMaxDynamicSharedMemorySize,
                         SMEM_BYTES);
    cudaFuncSetAttribute(proj_kernel, cudaFuncAttributeMaxDynamicSharedMemorySize,
                         smem2);

    xt_kernel<<<dim3(TT, 4), 128>>>(inputs);
    lstm_mma<<<NCTA_R, RTHREADS, SMEM_BYTES>>>(W_ih, W_hh, b_ih, b_hh);
    proj_kernel<<<(BB * TT) / PROJ_ROWS, NTHREADS, smem2>>>(V_w, V_b, out);
}